// round 5
// baseline (speedup 1.0000x reference)
#include <cuda_runtime.h>
#include <cstdint>

#define NN 10000
#define HH 128
#define EE 640000
#define E2 (EE + NN)

typedef unsigned long long ull;

// ---------------- device scratch ----------------
__device__ float g_xl[NN * HH];
__device__ float g_xr[NN * HH];
__device__ float g_ez[E2];
__device__ float g_denom[NN];
__device__ int   g_count[NN];
__device__ int   g_cursor[NN];
__device__ int   g_rowstart[NN + 1];
__device__ int   g_csr_src[E2];
__device__ float g_csr_ez[E2];
__device__ float g_hgat[NN * HH];
__device__ float g_gi[NN * 3 * HH];
__device__ float g_hseq[NN * HH];
__device__ float g_tmp[NN * HH];

// ---------------- helpers ----------------
__device__ __forceinline__ ull ffma2(ull a, ull b, ull c) {
    ull d;
    asm("fma.rn.f32x2 %0, %1, %2, %3;" : "=l"(d) : "l"(a), "l"(b), "l"(c));
    return d;
}
__device__ __forceinline__ ull fadd2(ull a, ull b) {
    ull d;
    asm("add.rn.f32x2 %0, %1, %2;" : "=l"(d) : "l"(a), "l"(b));
    return d;
}
__device__ __forceinline__ float unpack_sum(ull a) {
    unsigned lo, hi;
    asm("mov.b64 {%0,%1}, %2;" : "=r"(lo), "=r"(hi) : "l"(a));
    return __uint_as_float(lo) + __uint_as_float(hi);
}
__device__ __forceinline__ float sigf(float x) {
    return __fdividef(1.f, 1.f + __expf(-x));
}
__device__ __forceinline__ float tanhfast(float x) {
    return 2.f * __fdividef(1.f, 1.f + __expf(-2.f * x)) - 1.f;
}
__device__ __forceinline__ float lrelu(float v) {
    return v > 0.f ? v : 0.2f * v;
}
__device__ __forceinline__ int clampN(int v) {
    return v < 0 ? 0 : (v >= NN ? NN - 1 : v);
}
__device__ __forceinline__ uint32_t smem_u32(const void* p) {
    uint32_t a;
    asm("{ .reg .u64 t; cvta.to.shared.u64 t, %1; cvt.u32.u64 %0, t; }" : "=r"(a) : "l"(p));
    return a;
}

// ---------------- zero init ----------------
__global__ void zero_kernel() {
    int i = blockIdx.x * blockDim.x + threadIdx.x;
    if (i < NN) {
        g_denom[i] = 0.f;
        g_count[i] = 0;
        g_cursor[i] = 0;
    }
}

// ---------------- GEMM: C[M x P] = A[M x 128] @ W[P x 128]^T + bias ----------------
template <int P, bool RELU>
__global__ void __launch_bounds__(256) gemm_tn(const float* __restrict__ A,
                                               const float* __restrict__ W,
                                               const float* __restrict__ bias,
                                               float* __restrict__ C, int M) {
    __shared__ __align__(16) float As[32][68];
    __shared__ __align__(16) float Ws[32][68];
    const int tid = threadIdx.x;
    const int bm = blockIdx.x * 64;
    const int bp = blockIdx.y * 64;
    const int tx = tid & 15;
    const int ty = tid >> 4;
    float acc[4][4];
#pragma unroll
    for (int i = 0; i < 4; i++)
#pragma unroll
        for (int j = 0; j < 4; j++) acc[i][j] = 0.f;

    const int r = tid >> 3;
    const int kk = (tid & 7) * 4;

    for (int k0 = 0; k0 < 128; k0 += 32) {
#pragma unroll
        for (int rr = 0; rr < 64; rr += 32) {
            int row = bm + r + rr;
            float4 v = (row < M) ? *reinterpret_cast<const float4*>(A + (size_t)row * 128 + k0 + kk)
                                 : make_float4(0.f, 0.f, 0.f, 0.f);
            As[kk + 0][r + rr] = v.x;
            As[kk + 1][r + rr] = v.y;
            As[kk + 2][r + rr] = v.z;
            As[kk + 3][r + rr] = v.w;
            float4 wv = *reinterpret_cast<const float4*>(W + (size_t)(bp + r + rr) * 128 + k0 + kk);
            Ws[kk + 0][r + rr] = wv.x;
            Ws[kk + 1][r + rr] = wv.y;
            Ws[kk + 2][r + rr] = wv.z;
            Ws[kk + 3][r + rr] = wv.w;
        }
        __syncthreads();
#pragma unroll
        for (int k = 0; k < 32; k++) {
            const float4 av = *reinterpret_cast<const float4*>(&As[k][ty << 2]);
            const float4 wv = *reinterpret_cast<const float4*>(&Ws[k][tx << 2]);
            float a4[4] = {av.x, av.y, av.z, av.w};
            float w4[4] = {wv.x, wv.y, wv.z, wv.w};
#pragma unroll
            for (int i = 0; i < 4; i++)
#pragma unroll
                for (int j = 0; j < 4; j++) acc[i][j] += a4[i] * w4[j];
        }
        __syncthreads();
    }

    const int col0 = bp + (tx << 2);
    const float4 bv = *reinterpret_cast<const float4*>(bias + col0);
    float b4[4] = {bv.x, bv.y, bv.z, bv.w};
#pragma unroll
    for (int i = 0; i < 4; i++) {
        int row = bm + (ty << 2) + i;
        if (row < M) {
            float4 o;
            float v0 = acc[i][0] + b4[0];
            float v1 = acc[i][1] + b4[1];
            float v2 = acc[i][2] + b4[2];
            float v3 = acc[i][3] + b4[3];
            if (RELU) {
                v0 = fmaxf(v0, 0.f); v1 = fmaxf(v1, 0.f);
                v2 = fmaxf(v2, 0.f); v3 = fmaxf(v3, 0.f);
            }
            o.x = v0; o.y = v1; o.z = v2; o.w = v3;
            *reinterpret_cast<float4*>(C + (size_t)row * P + col0) = o;
        }
    }
}

// ---------------- edge logits ----------------
__global__ void __launch_bounds__(256) edge_kernel(const int* __restrict__ ei,
                                                   const float* __restrict__ att) {
    int e = blockIdx.x * 8 + (threadIdx.x >> 5);
    if (e >= E2) return;
    int lane = threadIdx.x & 31;
    int src, dst;
    if (e < EE) {
        src = clampN(ei[e]);
        dst = clampN(ei[EE + e]);
    } else {
        src = e - EE;
        dst = src;
    }
    const float4 a = *reinterpret_cast<const float4*>(g_xl + (size_t)src * HH + lane * 4);
    const float4 b = *reinterpret_cast<const float4*>(g_xr + (size_t)dst * HH + lane * 4);
    const float4 at = *reinterpret_cast<const float4*>(att + lane * 4);
    float s = lrelu(a.x + b.x) * at.x + lrelu(a.y + b.y) * at.y +
              lrelu(a.z + b.z) * at.z + lrelu(a.w + b.w) * at.w;
#pragma unroll
    for (int o = 16; o; o >>= 1) s += __shfl_xor_sync(0xffffffffu, s, o);
    if (lane == 0) {
        float ez = __expf(s);
        g_ez[e] = ez;
        atomicAdd(&g_denom[dst], ez);
        atomicAdd(&g_count[dst], 1);
    }
}

// ---------------- exclusive scan ----------------
__global__ void scan_kernel() {
    __shared__ int sh[256];
    const int t = threadIdx.x;
    const int PER = 40;
    const int base = t * PER;
    int s = 0;
    for (int i = 0; i < PER; i++) {
        int idx = base + i;
        if (idx < NN) s += g_count[idx];
    }
    sh[t] = s;
    __syncthreads();
    for (int o = 1; o < 256; o <<= 1) {
        int v = (t >= o) ? sh[t - o] : 0;
        __syncthreads();
        sh[t] += v;
        __syncthreads();
    }
    int run = sh[t] - s;
    for (int i = 0; i < PER; i++) {
        int idx = base + i;
        if (idx < NN) {
            g_rowstart[idx] = run;
            run += g_count[idx];
        }
    }
    if (t == 255) g_rowstart[NN] = sh[255];
}

// ---------------- fill CSR ----------------
__global__ void fill_kernel(const int* __restrict__ ei) {
    int e = blockIdx.x * blockDim.x + threadIdx.x;
    if (e >= E2) return;
    int src, dst;
    if (e < EE) {
        src = clampN(ei[e]);
        dst = clampN(ei[EE + e]);
    } else {
        src = e - EE;
        dst = src;
    }
    int pos = atomicAdd(&g_cursor[dst], 1);
    int idx = g_rowstart[dst] + pos;
    g_csr_src[idx] = src;
    g_csr_ez[idx] = g_ez[e];
}

// ---------------- aggregate ----------------
__global__ void __launch_bounds__(128) agg_kernel(const float* __restrict__ bconv) {
    const int n = blockIdx.x;
    const int t = threadIdx.x;
    __shared__ int   ssrc[128];
    __shared__ float sez[128];
    const int s = g_rowstart[n];
    const int e = g_rowstart[n + 1];
    float acc = 0.f;
    for (int p0 = s; p0 < e; p0 += 128) {
        int m = min(128, e - p0);
        if (t < m) {
            ssrc[t] = g_csr_src[p0 + t];
            sez[t] = g_csr_ez[p0 + t];
        }
        __syncthreads();
#pragma unroll 4
        for (int i = 0; i < m; i++) acc += sez[i] * g_xl[(size_t)ssrc[i] * HH + t];
        __syncthreads();
    }
    float v = acc / g_denom[n] + bconv[t];
    g_hgat[(size_t)n * HH + t] = fmaxf(v, 0.f);
}

// ---------------- sequential GRU: 2-CTA cluster, row-split ----------------
// CTA rank owns elements [64*rank, 64*rank+64). It computes the 192 W_hh rows
// feeding those elements (r: rows ebase+[0,64), z: 128+ebase+[0,64), n: 256+ebase+[0,64)).
// Thread map: idx = w*16 + (l&15) in [0,192), half = l>>4 (column half).
// Each thread: half-dot (64 cols) of its row; full dot via shfl.bfly(16).
// r/z threads compute sigmoids pre-barrier and STS; n threads do the combine,
// write hnew to own + peer smem (DSMEM), arrive on both mbarriers (count 128).
#define HOFF 68
__global__ void __launch_bounds__(384, 1) __cluster_dims__(2, 1, 1)
gru_kernel(const float* __restrict__ Whh,
           const float* __restrict__ bhh,
           const float* __restrict__ h0) {
    __shared__ __align__(16) float hsh[2][HOFF + 64];  // ping-pong h
    __shared__ float rz[128];                          // r[64], z[64]
    __shared__ __align__(8) ull mbar;
    const int t = threadIdx.x;
    const int w = t >> 5;
    const int l = t & 31;
    const int half = l >> 4;
    const int idx = w * 16 + (l & 15);   // 0..191
    const int gate = idx >> 6;           // 0=r,1=z,2=n
    const int eloc = idx & 63;
    uint32_t rank;
    asm("mov.u32 %0, %%cluster_ctarank;" : "=r"(rank));
    const int ebase = (int)rank * 64;
    const int eglob = ebase + eloc;
    const int grow = gate * 128 + eglob;   // global W_hh row

    // weights: half-row -> 32 packed f32x2
    ull wv[32];
    {
        const ulonglong2* p = reinterpret_cast<const ulonglong2*>(Whh + (size_t)grow * HH + 64 * half);
#pragma unroll
        for (int k = 0; k < 16; k++) {
            ulonglong2 v = p[k];
            wv[2 * k] = v.x;
            wv[2 * k + 1] = v.y;
        }
    }
    const float bh = bhh[grow];

    // mbarrier init + cluster sync
    uint32_t mbar_addr = smem_u32(&mbar);
    if (t == 0) {
        asm volatile("mbarrier.init.shared.b64 [%0], %1;" :: "r"(mbar_addr), "r"(128) : "memory");
    }
    // init h0 into buffer 0 (both CTAs load full h locally; no exchange)
    if (t < 64) hsh[0][t] = h0[t];
    else if (t < 128) hsh[0][HOFF + t - 64] = h0[t];
    __syncthreads();
    asm volatile("barrier.cluster.arrive.aligned;" ::: "memory");
    asm volatile("barrier.cluster.wait.aligned;" ::: "memory");

    // peer smem addresses for h write (element eglob position in hsh)
    const int hpos = (eglob < 64) ? eglob : (HOFF + eglob - 64);
    uint32_t my_h0 = smem_u32(&hsh[0][hpos]);
    uint32_t my_h1 = smem_u32(&hsh[1][hpos]);
    uint32_t peer_h0, peer_h1, peer_mbar;
    {
        uint32_t pr = 1u - rank;
        asm("mapa.shared::cluster.u32 %0, %1, %2;" : "=r"(peer_h0) : "r"(my_h0), "r"(pr));
        asm("mapa.shared::cluster.u32 %0, %1, %2;" : "=r"(peer_h1) : "r"(my_h1), "r"(pr));
        asm("mapa.shared::cluster.u32 %0, %1, %2;" : "=r"(peer_mbar) : "r"(mbar_addr), "r"(pr));
    }

    float hreg = (gate == 2) ? h0[eglob] : 0.f;
    float gi_cur = g_gi[(size_t)gate * HH + eglob];   // step 0

    for (int s = 0; s < NN; s++) {
        if (s > 0) {
            // wait for h(s-1): all local+remote arrivals of previous step
            uint32_t parity = (s - 1) & 1;
            uint32_t done;
            asm volatile(
                "{\n\t"
                ".reg .pred p;\n\t"
                "mbarrier.try_wait.parity.acquire.cluster.shared::cta.b64 p, [%1], %2;\n\t"
                "selp.b32 %0, 1, 0, p;\n\t"
                "}"
                : "=r"(done) : "r"(mbar_addr), "r"(parity) : "memory");
            if (!done) {
                asm volatile(
                    "{\n\t"
                    ".reg .pred P1;\n\t"
                    "WL_%=:\n\t"
                    "mbarrier.try_wait.parity.acquire.cluster.shared::cta.b64 P1, [%0], %1;\n\t"
                    "@P1 bra.uni WD_%=;\n\t"
                    "bra.uni WL_%=;\n\t"
                    "WD_%=:\n\t"
                    "}"
                    :: "r"(mbar_addr), "r"((s - 1) & 1) : "memory");
            }
        }
        const int cb = s & 1;
        // prefetch next step's gi
        float gi_next = 0.f;
        if (s + 1 < NN) gi_next = g_gi[(size_t)(s + 1) * (3 * HH) + gate * HH + eglob];

        // half-dot
        const ulonglong2* hp = reinterpret_cast<const ulonglong2*>(&hsh[cb][HOFF * half]);
        ull a0 = 0ull, a1 = 0ull;
#pragma unroll
        for (int k = 0; k < 16; k++) {
            ulonglong2 c = hp[k];
            a0 = ffma2(wv[2 * k], c.x, a0);
            a1 = ffma2(wv[2 * k + 1], c.y, a1);
        }
        float d = unpack_sum(fadd2(a0, a1));
        d += __shfl_xor_sync(0xffffffffu, d, 16);
        d += bh;   // full dot + bias of row grow

        if (gate == 0) {
            float r = sigf(gi_cur + d);
            if (half == 0) rz[eloc] = r;
        } else if (gate == 1) {
            float z = sigf(gi_cur + d);
            if (half == 0) rz[64 + eloc] = z;
        }
        __syncthreads();
        if (gate == 2) {
            float r = rz[eloc];
            float z = rz[64 + eloc];
            float nc = tanhfast(gi_cur + r * d);
            float hnew = nc + z * (hreg - nc);
            hreg = hnew;
            if (half == 0) {
                const int nb = (s + 1) & 1;
                hsh[nb][hpos] = hnew;
                uint32_t pa = nb ? peer_h1 : peer_h0;
                asm volatile("st.shared::cluster.f32 [%0], %1;" :: "r"(pa), "f"(hnew) : "memory");
                g_hseq[(size_t)s * HH + eglob] = hnew;
                // arrive: own + peer (release, cluster scope)
                asm volatile("mbarrier.arrive.release.cluster.shared::cta.b64 _, [%0];"
                             :: "r"(mbar_addr) : "memory");
                asm volatile("mbarrier.arrive.release.cluster.shared::cluster.b64 _, [%0];"
                             :: "r"(peer_mbar) : "memory");
            }
        }
        gi_cur = gi_next;
    }

    // don't exit while peer traffic may be in flight
    asm volatile("barrier.cluster.arrive.aligned;" ::: "memory");
    asm volatile("barrier.cluster.wait.aligned;" ::: "memory");
}

// ---------------- final head ----------------
__global__ void __launch_bounds__(256) head_kernel(const float* __restrict__ W2,
                                                   const float* __restrict__ b2,
                                                   float* __restrict__ out) {
    int n = blockIdx.x * 8 + (threadIdx.x >> 5);
    if (n >= NN) return;
    int lane = threadIdx.x & 31;
    float4 a = *reinterpret_cast<const float4*>(g_tmp + (size_t)n * HH + lane * 4);
    float4 w = *reinterpret_cast<const float4*>(W2 + lane * 4);
    float s = a.x * w.x + a.y * w.y + a.z * w.z + a.w * w.w;
#pragma unroll
    for (int o = 16; o; o >>= 1) s += __shfl_xor_sync(0xffffffffu, s, o);
    if (lane == 0) out[n] = s + b2[0];
}

// ---------------- launch ----------------
extern "C" void kernel_launch(void* const* d_in, const int* in_sizes, int n_in,
                              void* d_out, int out_size) {
    const float* x      = (const float*)d_in[0];
    const int*   ei     = (const int*)d_in[1];
    const float* Wl     = (const float*)d_in[2];
    const float* bl     = (const float*)d_in[3];
    const float* Wr     = (const float*)d_in[4];
    const float* br     = (const float*)d_in[5];
    const float* att    = (const float*)d_in[6];
    const float* bconv  = (const float*)d_in[7];
    const float* Wih    = (const float*)d_in[8];
    const float* Whh    = (const float*)d_in[9];
    const float* bih    = (const float*)d_in[10];
    const float* bhh    = (const float*)d_in[11];
    const float* h0     = (const float*)d_in[12];
    const float* Wlin   = (const float*)d_in[13];
    const float* blin   = (const float*)d_in[14];
    const float* Wlin2  = (const float*)d_in[15];
    const float* blin2  = (const float*)d_in[16];
    float* out = (float*)d_out;

    float *xl_p, *xr_p, *hgat_p, *gi_p, *hseq_p, *tmp_p;
    cudaGetSymbolAddress((void**)&xl_p,   g_xl);
    cudaGetSymbolAddress((void**)&xr_p,   g_xr);
    cudaGetSymbolAddress((void**)&hgat_p, g_hgat);
    cudaGetSymbolAddress((void**)&gi_p,   g_gi);
    cudaGetSymbolAddress((void**)&hseq_p, g_hseq);
    cudaGetSymbolAddress((void**)&tmp_p,  g_tmp);

    const int MB = (NN + 63) / 64;

    zero_kernel<<<(NN + 255) / 256, 256>>>();

    gemm_tn<128, false><<<dim3(MB, 2), 256>>>(x, Wl, bl, xl_p, NN);
    gemm_tn<128, false><<<dim3(MB, 2), 256>>>(x, Wr, br, xr_p, NN);

    edge_kernel<<<(E2 + 7) / 8, 256>>>(ei, att);
    scan_kernel<<<1, 256>>>();
    fill_kernel<<<(E2 + 255) / 256, 256>>>(ei);
    agg_kernel<<<NN, 128>>>(bconv);

    gemm_tn<384, false><<<dim3(MB, 6), 256>>>(hgat_p, Wih, bih, gi_p, NN);

    gru_kernel<<<2, 384>>>(Whh, bhh, h0);

    gemm_tn<128, true><<<dim3(MB, 2), 256>>>(hseq_p, Wlin, blin, tmp_p, NN);
    head_kernel<<<(NN + 7) / 8, 256>>>(Wlin2, blin2, out);
}

// round 8
// speedup vs baseline: 1.7399x; 1.7399x over previous
#include <cuda_runtime.h>
#include <cstdint>

#define NN 10000
#define HH 128
#define EE 640000
#define E2 (EE + NN)

typedef unsigned long long ull;

// ---------------- device scratch ----------------
__device__ float g_xl[NN * HH];
__device__ float g_xr[NN * HH];
__device__ float g_ez[E2];
__device__ float g_denom[NN];
__device__ int   g_count[NN];
__device__ int   g_cursor[NN];
__device__ int   g_rowstart[NN + 1];
__device__ int   g_csr_src[E2];
__device__ float g_csr_ez[E2];
__device__ float g_hgat[NN * HH];
__device__ float g_gi[NN * 3 * HH];
__device__ float g_hseq[NN * HH];
__device__ float g_tmp[NN * HH];

// ---------------- helpers ----------------
__device__ __forceinline__ ull ffma2(ull a, ull b, ull c) {
    ull d;
    asm("fma.rn.f32x2 %0, %1, %2, %3;" : "=l"(d) : "l"(a), "l"(b), "l"(c));
    return d;
}
__device__ __forceinline__ ull fadd2(ull a, ull b) {
    ull d;
    asm("add.rn.f32x2 %0, %1, %2;" : "=l"(d) : "l"(a), "l"(b));
    return d;
}
__device__ __forceinline__ float unpack_sum(ull a) {
    unsigned lo, hi;
    asm("mov.b64 {%0,%1}, %2;" : "=r"(lo), "=r"(hi) : "l"(a));
    return __uint_as_float(lo) + __uint_as_float(hi);
}
__device__ __forceinline__ float sigf(float x) {
    return __fdividef(1.f, 1.f + __expf(-x));
}
__device__ __forceinline__ float tanhfast(float x) {
    return 2.f * __fdividef(1.f, 1.f + __expf(-2.f * x)) - 1.f;
}
__device__ __forceinline__ float lrelu(float v) {
    return v > 0.f ? v : 0.2f * v;
}
__device__ __forceinline__ int clampN(int v) {
    return v < 0 ? 0 : (v >= NN ? NN - 1 : v);
}

// ---------------- zero init ----------------
__global__ void zero_kernel() {
    int i = blockIdx.x * blockDim.x + threadIdx.x;
    if (i < NN) {
        g_denom[i] = 0.f;
        g_count[i] = 0;
        g_cursor[i] = 0;
    }
}

// ---------------- GEMM: C[M x P] = A[M x 128] @ W[P x 128]^T + bias ----------------
template <int P, bool RELU>
__global__ void __launch_bounds__(256) gemm_tn(const float* __restrict__ A,
                                               const float* __restrict__ W,
                                               const float* __restrict__ bias,
                                               float* __restrict__ C, int M) {
    __shared__ __align__(16) float As[32][68];
    __shared__ __align__(16) float Ws[32][68];
    const int tid = threadIdx.x;
    const int bm = blockIdx.x * 64;
    const int bp = blockIdx.y * 64;
    const int tx = tid & 15;
    const int ty = tid >> 4;
    float acc[4][4];
#pragma unroll
    for (int i = 0; i < 4; i++)
#pragma unroll
        for (int j = 0; j < 4; j++) acc[i][j] = 0.f;

    const int r = tid >> 3;
    const int kk = (tid & 7) * 4;

    for (int k0 = 0; k0 < 128; k0 += 32) {
#pragma unroll
        for (int rr = 0; rr < 64; rr += 32) {
            int row = bm + r + rr;
            float4 v = (row < M) ? *reinterpret_cast<const float4*>(A + (size_t)row * 128 + k0 + kk)
                                 : make_float4(0.f, 0.f, 0.f, 0.f);
            As[kk + 0][r + rr] = v.x;
            As[kk + 1][r + rr] = v.y;
            As[kk + 2][r + rr] = v.z;
            As[kk + 3][r + rr] = v.w;
            float4 wv = *reinterpret_cast<const float4*>(W + (size_t)(bp + r + rr) * 128 + k0 + kk);
            Ws[kk + 0][r + rr] = wv.x;
            Ws[kk + 1][r + rr] = wv.y;
            Ws[kk + 2][r + rr] = wv.z;
            Ws[kk + 3][r + rr] = wv.w;
        }
        __syncthreads();
#pragma unroll
        for (int k = 0; k < 32; k++) {
            const float4 av = *reinterpret_cast<const float4*>(&As[k][ty << 2]);
            const float4 wv = *reinterpret_cast<const float4*>(&Ws[k][tx << 2]);
            float a4[4] = {av.x, av.y, av.z, av.w};
            float w4[4] = {wv.x, wv.y, wv.z, wv.w};
#pragma unroll
            for (int i = 0; i < 4; i++)
#pragma unroll
                for (int j = 0; j < 4; j++) acc[i][j] += a4[i] * w4[j];
        }
        __syncthreads();
    }

    const int col0 = bp + (tx << 2);
    const float4 bv = *reinterpret_cast<const float4*>(bias + col0);
    float b4[4] = {bv.x, bv.y, bv.z, bv.w};
#pragma unroll
    for (int i = 0; i < 4; i++) {
        int row = bm + (ty << 2) + i;
        if (row < M) {
            float4 o;
            float v0 = acc[i][0] + b4[0];
            float v1 = acc[i][1] + b4[1];
            float v2 = acc[i][2] + b4[2];
            float v3 = acc[i][3] + b4[3];
            if (RELU) {
                v0 = fmaxf(v0, 0.f); v1 = fmaxf(v1, 0.f);
                v2 = fmaxf(v2, 0.f); v3 = fmaxf(v3, 0.f);
            }
            o.x = v0; o.y = v1; o.z = v2; o.w = v3;
            *reinterpret_cast<float4*>(C + (size_t)row * P + col0) = o;
        }
    }
}

// ---------------- edge logits ----------------
__global__ void __launch_bounds__(256) edge_kernel(const int* __restrict__ ei,
                                                   const float* __restrict__ att) {
    int e = blockIdx.x * 8 + (threadIdx.x >> 5);
    if (e >= E2) return;
    int lane = threadIdx.x & 31;
    int src, dst;
    if (e < EE) {
        src = clampN(ei[e]);
        dst = clampN(ei[EE + e]);
    } else {
        src = e - EE;
        dst = src;
    }
    const float4 a = *reinterpret_cast<const float4*>(g_xl + (size_t)src * HH + lane * 4);
    const float4 b = *reinterpret_cast<const float4*>(g_xr + (size_t)dst * HH + lane * 4);
    const float4 at = *reinterpret_cast<const float4*>(att + lane * 4);
    float s = lrelu(a.x + b.x) * at.x + lrelu(a.y + b.y) * at.y +
              lrelu(a.z + b.z) * at.z + lrelu(a.w + b.w) * at.w;
#pragma unroll
    for (int o = 16; o; o >>= 1) s += __shfl_xor_sync(0xffffffffu, s, o);
    if (lane == 0) {
        float ez = __expf(s);
        g_ez[e] = ez;
        atomicAdd(&g_denom[dst], ez);
        atomicAdd(&g_count[dst], 1);
    }
}

// ---------------- exclusive scan ----------------
__global__ void scan_kernel() {
    __shared__ int sh[256];
    const int t = threadIdx.x;
    const int PER = 40;
    const int base = t * PER;
    int s = 0;
    for (int i = 0; i < PER; i++) {
        int idx = base + i;
        if (idx < NN) s += g_count[idx];
    }
    sh[t] = s;
    __syncthreads();
    for (int o = 1; o < 256; o <<= 1) {
        int v = (t >= o) ? sh[t - o] : 0;
        __syncthreads();
        sh[t] += v;
        __syncthreads();
    }
    int run = sh[t] - s;
    for (int i = 0; i < PER; i++) {
        int idx = base + i;
        if (idx < NN) {
            g_rowstart[idx] = run;
            run += g_count[idx];
        }
    }
    if (t == 255) g_rowstart[NN] = sh[255];
}

// ---------------- fill CSR ----------------
__global__ void fill_kernel(const int* __restrict__ ei) {
    int e = blockIdx.x * blockDim.x + threadIdx.x;
    if (e >= E2) return;
    int src, dst;
    if (e < EE) {
        src = clampN(ei[e]);
        dst = clampN(ei[EE + e]);
    } else {
        src = e - EE;
        dst = src;
    }
    int pos = atomicAdd(&g_cursor[dst], 1);
    int idx = g_rowstart[dst] + pos;
    g_csr_src[idx] = src;
    g_csr_ez[idx] = g_ez[e];
}

// ---------------- aggregate ----------------
__global__ void __launch_bounds__(128) agg_kernel(const float* __restrict__ bconv) {
    const int n = blockIdx.x;
    const int t = threadIdx.x;
    __shared__ int   ssrc[128];
    __shared__ float sez[128];
    const int s = g_rowstart[n];
    const int e = g_rowstart[n + 1];
    float acc = 0.f;
    for (int p0 = s; p0 < e; p0 += 128) {
        int m = min(128, e - p0);
        if (t < m) {
            ssrc[t] = g_csr_src[p0 + t];
            sez[t] = g_csr_ez[p0 + t];
        }
        __syncthreads();
#pragma unroll 4
        for (int i = 0; i < m; i++) acc += sez[i] * g_xl[(size_t)ssrc[i] * HH + t];
        __syncthreads();
    }
    float v = acc / g_denom[n] + bconv[t];
    g_hgat[(size_t)n * HH + t] = fmaxf(v, 0.f);
}

// ---------------- sequential GRU: single CTA, full-row threads, 2 __syncthreads/step ----
// 384 threads, thread = one W_hh row (64 FFMA2, W in 128 regs, h broadcast LDS).
//   warps 0-3  (t in [0,128)):   n-rows (row 256+e), e = t        -- consumers
//   warps 4-7  (t in [128,256)): r-rows (row e),     e = t-128    -- producers
//   warps 8-11 (t in [256,384)): z-rows (row 128+e), e = t-256    -- producers
// Producers compute sigmoid pre-barrier and STS to rzsh.
// After sync 1 (all dots done), consumers combine and overwrite h in place.
// High-wid warps issue first (arbiter) => producer dots retire early.
__global__ void __launch_bounds__(384, 1) gru_kernel(const float* __restrict__ Whh,
                                                     const float* __restrict__ bhh,
                                                     const float* __restrict__ h0) {
    __shared__ __align__(16) float hsh[128];   // current h (in-place update)
    __shared__ float rzsh[256];                // r: [0,128), z: [128,256)
    const int t = threadIdx.x;
    const bool isN = (t < 128);
    const int e = isN ? t : ((t < 256) ? (t - 128) : (t - 256));
    const int gate = isN ? 2 : ((t < 256) ? 0 : 1);   // 0=r,1=z,2=n
    const int row = gate * 128 + e;                   // W_hh row index

    // W row -> 64 packed f32x2 registers
    ull w[64];
    {
        const ulonglong2* wr = reinterpret_cast<const ulonglong2*>(Whh + (size_t)row * HH);
#pragma unroll
        for (int i = 0; i < 32; i++) {
            ulonglong2 v = wr[i];
            w[2 * i] = v.x;
            w[2 * i + 1] = v.y;
        }
    }
    const float bh = bhh[row];
    const float* giBase = g_gi + (size_t)gate * HH + e;   // + s*384 per step

    float hreg = 0.f;
    if (isN) {
        hreg = h0[e];
        hsh[e] = hreg;
    }
    float gi_cur = giBase[0];
    __syncthreads();

    const ulonglong2* hp = reinterpret_cast<const ulonglong2*>(hsh);

    for (int s = 0; s < NN; s++) {
        // prefetch next step's gi (hidden under dot)
        float gi_next = 0.f;
        if (s + 1 < NN) gi_next = giBase[(size_t)(s + 1) * (3 * HH)];

        // full-row dot, rotating 2-ahead h loads (broadcast LDS.128)
        ull a0 = 0ull, a1 = 0ull;
        ulonglong2 c0 = hp[0];
        ulonglong2 c1 = hp[1];
#pragma unroll
        for (int i = 0; i < 32; i++) {
            ulonglong2 cur = c0;
            c0 = c1;
            if (i + 2 < 32) c1 = hp[i + 2];
            a0 = ffma2(w[2 * i], cur.x, a0);
            a1 = ffma2(w[2 * i + 1], cur.y, a1);
        }
        float d = unpack_sum(fadd2(a0, a1)) + bh;

        if (!isN) {
            float sg = sigf(gi_cur + d);   // sigmoid for r/z computed pre-barrier
            rzsh[t - 128] = sg;            // r -> [0,128), z -> [128,256)
        }
        __syncthreads();                   // all dots done; rzsh visible
        if (isN) {
            float r = rzsh[e];
            float z = rzsh[128 + e];
            float nc = tanhfast(gi_cur + r * d);
            float hnew = nc + z * (hreg - nc);
            hreg = hnew;
            hsh[e] = hnew;                 // safe: every dot finished before sync
            g_hseq[(size_t)s * HH + e] = hnew;
        }
        __syncthreads();                   // h published
        gi_cur = gi_next;
    }
}

// ---------------- final head ----------------
__global__ void __launch_bounds__(256) head_kernel(const float* __restrict__ W2,
                                                   const float* __restrict__ b2,
                                                   float* __restrict__ out) {
    int n = blockIdx.x * 8 + (threadIdx.x >> 5);
    if (n >= NN) return;
    int lane = threadIdx.x & 31;
    float4 a = *reinterpret_cast<const float4*>(g_tmp + (size_t)n * HH + lane * 4);
    float4 w = *reinterpret_cast<const float4*>(W2 + lane * 4);
    float s = a.x * w.x + a.y * w.y + a.z * w.z + a.w * w.w;
#pragma unroll
    for (int o = 16; o; o >>= 1) s += __shfl_xor_sync(0xffffffffu, s, o);
    if (lane == 0) out[n] = s + b2[0];
}

// ---------------- launch ----------------
extern "C" void kernel_launch(void* const* d_in, const int* in_sizes, int n_in,
                              void* d_out, int out_size) {
    const float* x      = (const float*)d_in[0];
    const int*   ei     = (const int*)d_in[1];
    const float* Wl     = (const float*)d_in[2];
    const float* bl     = (const float*)d_in[3];
    const float* Wr     = (const float*)d_in[4];
    const float* br     = (const float*)d_in[5];
    const float* att    = (const float*)d_in[6];
    const float* bconv  = (const float*)d_in[7];
    const float* Wih    = (const float*)d_in[8];
    const float* Whh    = (const float*)d_in[9];
    const float* bih    = (const float*)d_in[10];
    const float* bhh    = (const float*)d_in[11];
    const float* h0     = (const float*)d_in[12];
    const float* Wlin   = (const float*)d_in[13];
    const float* blin   = (const float*)d_in[14];
    const float* Wlin2  = (const float*)d_in[15];
    const float* blin2  = (const float*)d_in[16];
    float* out = (float*)d_out;

    float *xl_p, *xr_p, *hgat_p, *gi_p, *hseq_p, *tmp_p;
    cudaGetSymbolAddress((void**)&xl_p,   g_xl);
    cudaGetSymbolAddress((void**)&xr_p,   g_xr);
    cudaGetSymbolAddress((void**)&hgat_p, g_hgat);
    cudaGetSymbolAddress((void**)&gi_p,   g_gi);
    cudaGetSymbolAddress((void**)&hseq_p, g_hseq);
    cudaGetSymbolAddress((void**)&tmp_p,  g_tmp);

    const int MB = (NN + 63) / 64;

    zero_kernel<<<(NN + 255) / 256, 256>>>();

    gemm_tn<128, false><<<dim3(MB, 2), 256>>>(x, Wl, bl, xl_p, NN);
    gemm_tn<128, false><<<dim3(MB, 2), 256>>>(x, Wr, br, xr_p, NN);

    edge_kernel<<<(E2 + 7) / 8, 256>>>(ei, att);
    scan_kernel<<<1, 256>>>();
    fill_kernel<<<(E2 + 255) / 256, 256>>>(ei);
    agg_kernel<<<NN, 128>>>(bconv);

    gemm_tn<384, false><<<dim3(MB, 6), 256>>>(hgat_p, Wih, bih, gi_p, NN);

    gru_kernel<<<1, 384>>>(Whh, bhh, h0);

    gemm_tn<128, true><<<dim3(MB, 2), 256>>>(hseq_p, Wlin, blin, tmp_p, NN);
    head_kernel<<<(NN + 7) / 8, 256>>>(Wlin2, blin2, out);
}

// round 9
// speedup vs baseline: 2.0517x; 1.1792x over previous
#include <cuda_runtime.h>
#include <cstdint>

#define NN 10000
#define HH 128
#define EE 640000
#define E2 (EE + NN)

typedef unsigned long long ull;

// ---------------- device scratch ----------------
__device__ float g_xl[NN * HH];
__device__ float g_xr[NN * HH];
__device__ float g_ez[E2];
__device__ float g_denom[NN];
__device__ int   g_count[NN];
__device__ int   g_cursor[NN];
__device__ int   g_rowstart[NN + 1];
__device__ int   g_csr_src[E2];
__device__ float g_csr_ez[E2];
__device__ float g_hgat[NN * HH];
__device__ float g_gi[NN * 3 * HH];
__device__ float g_hseq[NN * HH];
__device__ float g_tmp[NN * HH];

// ---------------- helpers ----------------
__device__ __forceinline__ ull ffma2(ull a, ull b, ull c) {
    ull d;
    asm("fma.rn.f32x2 %0, %1, %2, %3;" : "=l"(d) : "l"(a), "l"(b), "l"(c));
    return d;
}
__device__ __forceinline__ ull fadd2(ull a, ull b) {
    ull d;
    asm("add.rn.f32x2 %0, %1, %2;" : "=l"(d) : "l"(a), "l"(b));
    return d;
}
__device__ __forceinline__ float unpack_sum(ull a) {
    unsigned lo, hi;
    asm("mov.b64 {%0,%1}, %2;" : "=r"(lo), "=r"(hi) : "l"(a));
    return __uint_as_float(lo) + __uint_as_float(hi);
}
__device__ __forceinline__ float sigf(float x) {
    return __fdividef(1.f, 1.f + __expf(-x));
}
__device__ __forceinline__ float tanhfast(float x) {
    return 2.f * __fdividef(1.f, 1.f + __expf(-2.f * x)) - 1.f;
}
__device__ __forceinline__ float lrelu(float v) {
    return v > 0.f ? v : 0.2f * v;
}
__device__ __forceinline__ int clampN(int v) {
    return v < 0 ? 0 : (v >= NN ? NN - 1 : v);
}

// ---------------- zero init ----------------
__global__ void zero_kernel() {
    int i = blockIdx.x * blockDim.x + threadIdx.x;
    if (i < NN) {
        g_denom[i] = 0.f;
        g_count[i] = 0;
        g_cursor[i] = 0;
    }
}

// ---------------- GEMM: C[M x P] = A[M x 128] @ W[P x 128]^T + bias ----------------
template <int P, bool RELU>
__global__ void __launch_bounds__(256) gemm_tn(const float* __restrict__ A,
                                               const float* __restrict__ W,
                                               const float* __restrict__ bias,
                                               float* __restrict__ C, int M) {
    __shared__ __align__(16) float As[32][68];
    __shared__ __align__(16) float Ws[32][68];
    const int tid = threadIdx.x;
    const int bm = blockIdx.x * 64;
    const int bp = blockIdx.y * 64;
    const int tx = tid & 15;
    const int ty = tid >> 4;
    float acc[4][4];
#pragma unroll
    for (int i = 0; i < 4; i++)
#pragma unroll
        for (int j = 0; j < 4; j++) acc[i][j] = 0.f;

    const int r = tid >> 3;
    const int kk = (tid & 7) * 4;

    for (int k0 = 0; k0 < 128; k0 += 32) {
#pragma unroll
        for (int rr = 0; rr < 64; rr += 32) {
            int row = bm + r + rr;
            float4 v = (row < M) ? *reinterpret_cast<const float4*>(A + (size_t)row * 128 + k0 + kk)
                                 : make_float4(0.f, 0.f, 0.f, 0.f);
            As[kk + 0][r + rr] = v.x;
            As[kk + 1][r + rr] = v.y;
            As[kk + 2][r + rr] = v.z;
            As[kk + 3][r + rr] = v.w;
            float4 wv = *reinterpret_cast<const float4*>(W + (size_t)(bp + r + rr) * 128 + k0 + kk);
            Ws[kk + 0][r + rr] = wv.x;
            Ws[kk + 1][r + rr] = wv.y;
            Ws[kk + 2][r + rr] = wv.z;
            Ws[kk + 3][r + rr] = wv.w;
        }
        __syncthreads();
#pragma unroll
        for (int k = 0; k < 32; k++) {
            const float4 av = *reinterpret_cast<const float4*>(&As[k][ty << 2]);
            const float4 wv = *reinterpret_cast<const float4*>(&Ws[k][tx << 2]);
            float a4[4] = {av.x, av.y, av.z, av.w};
            float w4[4] = {wv.x, wv.y, wv.z, wv.w};
#pragma unroll
            for (int i = 0; i < 4; i++)
#pragma unroll
                for (int j = 0; j < 4; j++) acc[i][j] += a4[i] * w4[j];
        }
        __syncthreads();
    }

    const int col0 = bp + (tx << 2);
    const float4 bv = *reinterpret_cast<const float4*>(bias + col0);
    float b4[4] = {bv.x, bv.y, bv.z, bv.w};
#pragma unroll
    for (int i = 0; i < 4; i++) {
        int row = bm + (ty << 2) + i;
        if (row < M) {
            float4 o;
            float v0 = acc[i][0] + b4[0];
            float v1 = acc[i][1] + b4[1];
            float v2 = acc[i][2] + b4[2];
            float v3 = acc[i][3] + b4[3];
            if (RELU) {
                v0 = fmaxf(v0, 0.f); v1 = fmaxf(v1, 0.f);
                v2 = fmaxf(v2, 0.f); v3 = fmaxf(v3, 0.f);
            }
            o.x = v0; o.y = v1; o.z = v2; o.w = v3;
            *reinterpret_cast<float4*>(C + (size_t)row * P + col0) = o;
        }
    }
}

// ---------------- edge logits ----------------
__global__ void __launch_bounds__(256) edge_kernel(const int* __restrict__ ei,
                                                   const float* __restrict__ att) {
    int e = blockIdx.x * 8 + (threadIdx.x >> 5);
    if (e >= E2) return;
    int lane = threadIdx.x & 31;
    int src, dst;
    if (e < EE) {
        src = clampN(ei[e]);
        dst = clampN(ei[EE + e]);
    } else {
        src = e - EE;
        dst = src;
    }
    const float4 a = *reinterpret_cast<const float4*>(g_xl + (size_t)src * HH + lane * 4);
    const float4 b = *reinterpret_cast<const float4*>(g_xr + (size_t)dst * HH + lane * 4);
    const float4 at = *reinterpret_cast<const float4*>(att + lane * 4);
    float s = lrelu(a.x + b.x) * at.x + lrelu(a.y + b.y) * at.y +
              lrelu(a.z + b.z) * at.z + lrelu(a.w + b.w) * at.w;
#pragma unroll
    for (int o = 16; o; o >>= 1) s += __shfl_xor_sync(0xffffffffu, s, o);
    if (lane == 0) {
        float ez = __expf(s);
        g_ez[e] = ez;
        atomicAdd(&g_denom[dst], ez);
        atomicAdd(&g_count[dst], 1);
    }
}

// ---------------- exclusive scan ----------------
__global__ void scan_kernel() {
    __shared__ int sh[256];
    const int t = threadIdx.x;
    const int PER = 40;
    const int base = t * PER;
    int s = 0;
    for (int i = 0; i < PER; i++) {
        int idx = base + i;
        if (idx < NN) s += g_count[idx];
    }
    sh[t] = s;
    __syncthreads();
    for (int o = 1; o < 256; o <<= 1) {
        int v = (t >= o) ? sh[t - o] : 0;
        __syncthreads();
        sh[t] += v;
        __syncthreads();
    }
    int run = sh[t] - s;
    for (int i = 0; i < PER; i++) {
        int idx = base + i;
        if (idx < NN) {
            g_rowstart[idx] = run;
            run += g_count[idx];
        }
    }
    if (t == 255) g_rowstart[NN] = sh[255];
}

// ---------------- fill CSR ----------------
__global__ void fill_kernel(const int* __restrict__ ei) {
    int e = blockIdx.x * blockDim.x + threadIdx.x;
    if (e >= E2) return;
    int src, dst;
    if (e < EE) {
        src = clampN(ei[e]);
        dst = clampN(ei[EE + e]);
    } else {
        src = e - EE;
        dst = src;
    }
    int pos = atomicAdd(&g_cursor[dst], 1);
    int idx = g_rowstart[dst] + pos;
    g_csr_src[idx] = src;
    g_csr_ez[idx] = g_ez[e];
}

// ---------------- aggregate ----------------
__global__ void __launch_bounds__(128) agg_kernel(const float* __restrict__ bconv) {
    const int n = blockIdx.x;
    const int t = threadIdx.x;
    __shared__ int   ssrc[128];
    __shared__ float sez[128];
    const int s = g_rowstart[n];
    const int e = g_rowstart[n + 1];
    float acc = 0.f;
    for (int p0 = s; p0 < e; p0 += 128) {
        int m = min(128, e - p0);
        if (t < m) {
            ssrc[t] = g_csr_src[p0 + t];
            sez[t] = g_csr_ez[p0 + t];
        }
        __syncthreads();
#pragma unroll 4
        for (int i = 0; i < m; i++) acc += sez[i] * g_xl[(size_t)ssrc[i] * HH + t];
        __syncthreads();
    }
    float v = acc / g_denom[n] + bconv[t];
    g_hgat[(size_t)n * HH + t] = fmaxf(v, 0.f);
}

// ---------------- sequential GRU: R4 dot structure + producer/consumer gates ----------
// 384 threads. Warp w, lane l: half = l>>4, ip = w*16+(l&15) in [0,192).
// Thread computes half-dots (cols [64*half,64*half+64)) of logical rows 2ip, 2ip+1;
// owns full dot of rho = 2ip+half after shfl.bfly(16).
// Logical row rho -> gate/element:
//   rho in [0,128):   n-row, e=rho,      W_hh row 256+rho   (warps 0-3,  consumers)
//   rho in [128,256): r-row, e=rho-128,  W_hh row rho-128   (warps 4-7,  producers)
//   rho in [256,384): z-row, e=rho-256,  W_hh row rho-128   (warps 8-11, producers)
// Producers: sigmoid pre-barrier -> rz2[e] (.x=r, .y=z). Consumers post-barrier:
// one LDS.64 + tanh chain + in-place h update. Hi-wid producers issue first.
#define HOFF 68   // halves of h skewed by 272B -> bank-disjoint dual broadcast
__global__ void __launch_bounds__(384, 1) gru_kernel(const float* __restrict__ Whh,
                                                     const float* __restrict__ bhh,
                                                     const float* __restrict__ h0) {
    __shared__ __align__(16) float hsh[HOFF + 64];  // [0,64): half0, [68,132): half1
    __shared__ float2 rz2[128];                     // per element: (r, z)
    const int t = threadIdx.x;
    const int w = t >> 5;
    const int l = t & 31;
    const int half = l >> 4;
    const int ip = w * 16 + (l & 15);   // 0..191
    const int rowA = 2 * ip;            // logical even row
    const int rho = rowA + half;        // owned logical row
    const bool isN = (rho < 128);
    const int e = isN ? rho : ((rho < 256) ? (rho - 128) : (rho - 256));
    const int gate = isN ? 2 : ((rho < 256) ? 0 : 1);   // gi index: 0=r,1=z,2=n

    // logical row -> W_hh row
    const int wrowA = (rowA < 128) ? (256 + rowA) : (rowA - 128);
    const int wrowB = wrowA + 1;   // rowA,rowA+1 in same 128-block -> same mapping
    // W: half-rows of wrowA and wrowB, 64 floats each -> 32 ull each (128 regs)
    ull wa[32], wb[32];
    {
        const ulonglong2* pa = reinterpret_cast<const ulonglong2*>(Whh + (size_t)wrowA * HH + 64 * half);
        const ulonglong2* pb = reinterpret_cast<const ulonglong2*>(Whh + (size_t)wrowB * HH + 64 * half);
#pragma unroll
        for (int k = 0; k < 16; k++) {
            ulonglong2 va = pa[k];
            ulonglong2 vb = pb[k];
            wa[2 * k] = va.x; wa[2 * k + 1] = va.y;
            wb[2 * k] = vb.x; wb[2 * k + 1] = vb.y;
        }
    }
    const float bh = bhh[(rho < 128) ? (256 + rho) : (rho - 128)];
    const float* giBase = g_gi + (size_t)gate * HH + e;

    float hreg = 0.f;
    if (isN) {
        hreg = h0[e];
        hsh[(e < 64) ? e : (HOFF - 64 + e)] = hreg;
    }
    float gi_cur = giBase[0];
    __syncthreads();

    const ulonglong2* hp = reinterpret_cast<const ulonglong2*>(hsh + HOFF * half);
    const int hpos = (e < 64) ? e : (HOFF - 64 + e);

    for (int s = 0; s < NN; s++) {
        // prefetch next step's gi (hidden under dot)
        float gi_next = 0.f;
        if (s + 1 < NN) gi_next = giBase[(size_t)(s + 1) * (3 * HH)];

        // half-dots of rows rowA, rowA+1 against my h half (plain loads; ptxas batches)
        ull a00 = 0ull, a01 = 0ull, a10 = 0ull, a11 = 0ull;
#pragma unroll
        for (int k = 0; k < 16; k++) {
            ulonglong2 c = hp[k];
            a00 = ffma2(wa[2 * k], c.x, a00);
            a01 = ffma2(wa[2 * k + 1], c.y, a01);
            a10 = ffma2(wb[2 * k], c.x, a10);
            a11 = ffma2(wb[2 * k + 1], c.y, a11);
        }
        float d0 = unpack_sum(fadd2(a00, a01));
        float d1 = unpack_sum(fadd2(a10, a11));
        d0 += __shfl_xor_sync(0xffffffffu, d0, 16);
        d1 += __shfl_xor_sync(0xffffffffu, d1, 16);
        float res = (half ? d1 : d0) + bh;   // full dot + bias of owned row

        if (!isN) {
            // producers: r/z sigmoid pre-barrier
            reinterpret_cast<float*>(rz2)[2 * e + gate] = sigf(gi_cur + res);
        }
        __syncthreads();                     // dots done; rz visible
        if (isN) {
            float2 v = rz2[e];
            float nc = tanhfast(gi_cur + v.x * res);
            float hnew = nc + v.y * (hreg - nc);
            hreg = hnew;
            hsh[hpos] = hnew;                // safe: all dots finished before sync
            g_hseq[(size_t)s * HH + e] = hnew;
        }
        __syncthreads();                     // h published
        gi_cur = gi_next;
    }
}

// ---------------- final head ----------------
__global__ void __launch_bounds__(256) head_kernel(const float* __restrict__ W2,
                                                   const float* __restrict__ b2,
                                                   float* __restrict__ out) {
    int n = blockIdx.x * 8 + (threadIdx.x >> 5);
    if (n >= NN) return;
    int lane = threadIdx.x & 31;
    float4 a = *reinterpret_cast<const float4*>(g_tmp + (size_t)n * HH + lane * 4);
    float4 w = *reinterpret_cast<const float4*>(W2 + lane * 4);
    float s = a.x * w.x + a.y * w.y + a.z * w.z + a.w * w.w;
#pragma unroll
    for (int o = 16; o; o >>= 1) s += __shfl_xor_sync(0xffffffffu, s, o);
    if (lane == 0) out[n] = s + b2[0];
}

// ---------------- launch ----------------
extern "C" void kernel_launch(void* const* d_in, const int* in_sizes, int n_in,
                              void* d_out, int out_size) {
    const float* x      = (const float*)d_in[0];
    const int*   ei     = (const int*)d_in[1];
    const float* Wl     = (const float*)d_in[2];
    const float* bl     = (const float*)d_in[3];
    const float* Wr     = (const float*)d_in[4];
    const float* br     = (const float*)d_in[5];
    const float* att    = (const float*)d_in[6];
    const float* bconv  = (const float*)d_in[7];
    const float* Wih    = (const float*)d_in[8];
    const float* Whh    = (const float*)d_in[9];
    const float* bih    = (const float*)d_in[10];
    const float* bhh    = (const float*)d_in[11];
    const float* h0     = (const float*)d_in[12];
    const float* Wlin   = (const float*)d_in[13];
    const float* blin   = (const float*)d_in[14];
    const float* Wlin2  = (const float*)d_in[15];
    const float* blin2  = (const float*)d_in[16];
    float* out = (float*)d_out;

    float *xl_p, *xr_p, *hgat_p, *gi_p, *hseq_p, *tmp_p;
    cudaGetSymbolAddress((void**)&xl_p,   g_xl);
    cudaGetSymbolAddress((void**)&xr_p,   g_xr);
    cudaGetSymbolAddress((void**)&hgat_p, g_hgat);
    cudaGetSymbolAddress((void**)&gi_p,   g_gi);
    cudaGetSymbolAddress((void**)&hseq_p, g_hseq);
    cudaGetSymbolAddress((void**)&tmp_p,  g_tmp);

    const int MB = (NN + 63) / 64;

    zero_kernel<<<(NN + 255) / 256, 256>>>();

    gemm_tn<128, false><<<dim3(MB, 2), 256>>>(x, Wl, bl, xl_p, NN);
    gemm_tn<128, false><<<dim3(MB, 2), 256>>>(x, Wr, br, xr_p, NN);

    edge_kernel<<<(E2 + 7) / 8, 256>>>(ei, att);
    scan_kernel<<<1, 256>>>();
    fill_kernel<<<(E2 + 255) / 256, 256>>>(ei);
    agg_kernel<<<NN, 128>>>(bconv);

    gemm_tn<384, false><<<dim3(MB, 6), 256>>>(hgat_p, Wih, bih, gi_p, NN);

    gru_kernel<<<1, 384>>>(Whh, bhh, h0);

    gemm_tn<128, true><<<dim3(MB, 2), 256>>>(hseq_p, Wlin, blin, tmp_p, NN);
    head_kernel<<<(NN + 7) / 8, 256>>>(Wlin2, blin2, out);
}